// round 5
// baseline (speedup 1.0000x reference)
#include <cuda_runtime.h>
#include <cuda_bf16.h>

#define HID 128
#define E_ 262144
#define N_ 32768
#define GEO_ 13
#define ROWS_MAX (E_ + 512)
#define GRID_G (ROWS_MAX / 128)

typedef unsigned long long u64;
typedef unsigned int u32;

// ---- dynamic smem layout ----
#define SA 136                     // padded row stride (elements)
#define ABYTES (128 * SA * 2)      // 34816
#define OFF_AHI 0
#define OFF_ALO 34816
#define OFF_BHI 69632
#define OFF_BLO 104448
#define OFF_SSB 139264
#define OFF_SSC 139776
#define OFF_SSH 140288
#define SMEM_NEED 140800

// ---------------- scratch (device globals; no allocation) ----------------
__device__ float g_hA[(size_t)ROWS_MAX * HID];
__device__ float g_hB[(size_t)ROWS_MAX * HID];
__device__ __nv_bfloat16 g_Wh[4 * 3 * 16384];    // layer weights [r*3+l][n][k]
__device__ __nv_bfloat16 g_Wl[4 * 3 * 16384];
__device__ __nv_bfloat16 g_W0h[4 * 3 * 16384];   // W0 k-chunks 0..2 [r*3+c][n][k]
__device__ __nv_bfloat16 g_W0l[4 * 3 * 16384];
__device__ __nv_bfloat16 g_W0gh[4 * 2048];       // W0 geo chunk [r][n][16]
__device__ __nv_bfloat16 g_W0gl[4 * 2048];
__device__ int   g_perm[ROWS_MAX];
__device__ int   g_route[E_];
__device__ int   g_cnt[4];
__device__ int   g_cur[4];
__device__ int   g_bnd[5];
__device__ float g_cntf[4];
__device__ float g_stats[4][4][HID][2];
__device__ float g_st[4][4][HID][2];

// ---------------- helpers ----------------
__device__ __forceinline__ u32 smem_u32(const void* p){
  u32 a; asm("{ .reg .u64 t; cvta.to.shared.u64 t, %1; cvt.u32.u64 %0, t; }" : "=r"(a) : "l"(p));
  return a;
}
__device__ __forceinline__ u32 cvt2(float hi, float lo){
  u32 r; asm("cvt.rn.bf16x2.f32 %0, %1, %2;" : "=r"(r) : "f"(hi), "f"(lo)); return r;
}
// pack 2 floats -> bf16x2 hi word + bf16x2 residual word. low 16 bits = element v0.
__device__ __forceinline__ void split2(float v0, float v1, u32& h, u32& l){
  h = cvt2(v1, v0);
  float f0 = __uint_as_float(h << 16);
  float f1 = __uint_as_float(h & 0xFFFF0000u);
  l = cvt2(v1 - f1, v0 - f0);
}
__device__ __forceinline__ void split_store4(char* bp, u32 offH, u32 offL, float4 v){
  u32 h01, l01, h23, l23;
  split2(v.x, v.y, h01, l01);
  split2(v.z, v.w, h23, l23);
  *(uint2*)(bp + offH) = make_uint2(h01, h23);
  *(uint2*)(bp + offL) = make_uint2(l01, l23);
}
__device__ __forceinline__ void ldm4(u32& r0, u32& r1, u32& r2, u32& r3, u32 addr){
  asm volatile("ldmatrix.sync.aligned.m8n8.x4.shared.b16 {%0,%1,%2,%3}, [%4];"
               : "=r"(r0), "=r"(r1), "=r"(r2), "=r"(r3) : "r"(addr));
}
__device__ __forceinline__ void mma16816(float* d, const u32* a, u32 b0, u32 b1){
  asm volatile("mma.sync.aligned.m16n8k16.row.col.f32.bf16.bf16.f32 "
               "{%0,%1,%2,%3}, {%4,%5,%6,%7}, {%8,%9}, {%0,%1,%2,%3};"
               : "+f"(d[0]), "+f"(d[1]), "+f"(d[2]), "+f"(d[3])
               : "r"(a[0]), "r"(a[1]), "r"(a[2]), "r"(a[3]), "r"(b0), "r"(b1));
}

// ---------------- init ----------------
__global__ void k_init(float* __restrict__ out){
  int idx = blockIdx.x * 256 + threadIdx.x;
  if (idx < N_ * HID) out[idx] = 0.f;
  if (idx < ROWS_MAX) g_perm[idx] = -1;
  if (idx < 4 * 4 * HID * 2) ((float*)g_stats)[idx] = 0.f;
  if (idx < 4) { g_cnt[idx] = 0; g_cur[idx] = 0; }
}

// ---------------- weight preprocessing: split-bf16, plain [n][k] ----------------
__global__ void k_prep(const float* __restrict__ W0, const float* __restrict__ W){
  int idx = blockIdx.x * 256 + threadIdx.x;
  const int NL = 4 * 3 * 16384;
  if (idx < NL){
    int rl = idx / 16384, rem = idx & 16383;
    int n = rem >> 7, k = rem & 127;
    float v = W[((size_t)(rl * 128 + n)) * 128 + k];
    u32 h, l; split2(v, 0.f, h, l);
    g_Wh[idx] = __ushort_as_bfloat16((unsigned short)(h & 0xFFFF));
    g_Wl[idx] = __ushort_as_bfloat16((unsigned short)(l & 0xFFFF));
  } else if (idx < 2 * NL){
    int t = idx - NL;
    int rc = t / 16384, rem = t & 16383;
    int r = rc / 3, c = rc % 3;
    int n = rem >> 7, k = rem & 127;
    int ko = c * 128 + k;
    float v = W0[((size_t)(r * 128 + n)) * 397 + ko];
    u32 h, l; split2(v, 0.f, h, l);
    g_W0h[t] = __ushort_as_bfloat16((unsigned short)(h & 0xFFFF));
    g_W0l[t] = __ushort_as_bfloat16((unsigned short)(l & 0xFFFF));
  } else if (idx < 2 * NL + 4 * 2048){
    int t = idx - 2 * NL;
    int r = t / 2048, rem = t & 2047;
    int n = rem >> 4, k = rem & 15;
    int ko = 384 + k;
    float v = (ko < 397) ? W0[((size_t)(r * 128 + n)) * 397 + ko] : 0.f;
    u32 h, l; split2(v, 0.f, h, l);
    g_W0gh[t] = __ushort_as_bfloat16((unsigned short)(h & 0xFFFF));
    g_W0gl[t] = __ushort_as_bfloat16((unsigned short)(l & 0xFFFF));
  }
}

// ---------------- routing / segmentation ----------------
__global__ void k_route(const int* __restrict__ eij, const int* __restrict__ ejk,
                        const int* __restrict__ nei_ptr){
  int e = blockIdx.x * 256 + threadIdx.x;
  if (e >= E_) return;
  int nei = nei_ptr[0];
  int r = ((eij[e] < nei) ? 0 : 2) | ((ejk[e] < nei) ? 0 : 1);
  g_route[e] = r;
  int lane = threadIdx.x & 31;
  #pragma unroll
  for (int rr = 0; rr < 4; rr++){
    unsigned m = __ballot_sync(0xFFFFFFFFu, r == rr);
    if (r == rr && lane == (__ffs(m) - 1)) atomicAdd(&g_cnt[rr], __popc(m));
  }
}
__global__ void k_offsets(){
  if (threadIdx.x == 0){
    int b = 0;
    #pragma unroll
    for (int r = 0; r < 4; r++){
      g_bnd[r] = b;
      int c = g_cnt[r];
      b += ((c + 127) / 128) * 128;
      g_cntf[r] = (c > 0) ? (float)c : 1.0f;
    }
    g_bnd[4] = b;
  }
}
__global__ void k_perm(){
  int e = blockIdx.x * 256 + threadIdx.x;
  if (e >= E_) return;
  int r = g_route[e];
  int lane = threadIdx.x & 31;
  #pragma unroll
  for (int rr = 0; rr < 4; rr++){
    unsigned m = __ballot_sync(0xFFFFFFFFu, r == rr);
    if (r == rr){
      int leader = __ffs(m) - 1;
      int base = 0;
      if (lane == leader) base = atomicAdd(&g_cur[rr], __popc(m));
      base = __shfl_sync(m, base, leader);
      unsigned lt = (lane == 0) ? 0u : (0xFFFFFFFFu >> (32 - lane));
      g_perm[g_bnd[rr] + base + __popc(m & lt)] = e;
    }
  }
}

// ---------------- HMMA mainloop over one staged K-chunk ----------------
__device__ __forceinline__ void mma_chunk(u32 sb, int mw, int nw, int lane, int nk,
                                          float acc[2][8][4]){
  for (int ks = 0; ks < nk; ks++){
    int k0 = ks * 16;
    u32 ah[2][4], al[2][4];
    #pragma unroll
    for (int im = 0; im < 2; im++){
      int row = mw + im * 16 + (lane & 15);
      int col = k0 + ((lane >> 4) << 3);
      u32 off = (u32)(row * SA + col) * 2;
      ldm4(ah[im][0], ah[im][1], ah[im][2], ah[im][3], sb + OFF_AHI + off);
      ldm4(al[im][0], al[im][1], al[im][2], al[im][3], sb + OFF_ALO + off);
    }
    u32 b[8][2];
    {
      int brow = nw + ((lane >> 4) << 3) + (lane & 7);
      int bcol = k0 + (((lane >> 3) & 1) << 3);
      #pragma unroll
      for (int g = 0; g < 4; g++){
        u32 off = (u32)((brow + g * 16) * SA + bcol) * 2;
        ldm4(b[2*g][0], b[2*g][1], b[2*g+1][0], b[2*g+1][1], sb + OFF_BHI + off);
      }
      #pragma unroll
      for (int im = 0; im < 2; im++)
        #pragma unroll
        for (int in = 0; in < 8; in++){
          mma16816(acc[im][in], ah[im], b[in][0], b[in][1]);
          mma16816(acc[im][in], al[im], b[in][0], b[in][1]);
        }
      #pragma unroll
      for (int g = 0; g < 4; g++){
        u32 off = (u32)((brow + g * 16) * SA + bcol) * 2;
        ldm4(b[2*g][0], b[2*g][1], b[2*g+1][0], b[2*g+1][1], sb + OFF_BLO + off);
      }
      #pragma unroll
      for (int im = 0; im < 2; im++)
        #pragma unroll
        for (int in = 0; in < 8; in++)
          mma16816(acc[im][in], ah[im], b[in][0], b[in][1]);
    }
  }
}

// ---------------- epilogue: bias + store + fused BN stats ----------------
__device__ __forceinline__ void epilogue_mma(float acc[2][8][4], char* bp,
                                             float* __restrict__ hout,
                                             int m0, int mw, int nw, int lane,
                                             int r, int layer, int nval){
  int gid = lane >> 2, tig = lane & 3;
  const float* ssb = (const float*)(bp + OFF_SSB);
  float sum[8][2], sq[8][2];
  #pragma unroll
  for (int in = 0; in < 8; in++){ sum[in][0] = sum[in][1] = sq[in][0] = sq[in][1] = 0.f; }
  #pragma unroll
  for (int im = 0; im < 2; im++){
    int lr0 = mw + im * 16 + gid;
    bool v0 = lr0 < nval, v1 = (lr0 + 8) < nval;
    #pragma unroll
    for (int in = 0; in < 8; in++){
      float* d = acc[im][in];
      int col = nw + in * 8 + tig * 2;
      float b0 = ssb[col], b1 = ssb[col + 1];
      float e0 = d[0] + b0, e1 = d[1] + b1, e2 = d[2] + b0, e3 = d[3] + b1;
      *(float2*)&hout[(size_t)(m0 + lr0) * HID + col]     = make_float2(e0, e1);
      *(float2*)&hout[(size_t)(m0 + lr0 + 8) * HID + col] = make_float2(e2, e3);
      float m0v = v0 ? e0 : 0.f, m1v = v0 ? e1 : 0.f;
      float m2v = v1 ? e2 : 0.f, m3v = v1 ? e3 : 0.f;
      sum[in][0] += m0v + m2v; sum[in][1] += m1v + m3v;
      sq[in][0]  += m0v * m0v + m2v * m2v;
      sq[in][1]  += m1v * m1v + m3v * m3v;
    }
  }
  #pragma unroll
  for (int off = 4; off <= 16; off <<= 1){
    #pragma unroll
    for (int in = 0; in < 8; in++){
      sum[in][0] += __shfl_xor_sync(0xFFFFFFFFu, sum[in][0], off);
      sum[in][1] += __shfl_xor_sync(0xFFFFFFFFu, sum[in][1], off);
      sq[in][0]  += __shfl_xor_sync(0xFFFFFFFFu, sq[in][0], off);
      sq[in][1]  += __shfl_xor_sync(0xFFFFFFFFu, sq[in][1], off);
    }
  }
  if (gid == 0){
    #pragma unroll
    for (int in = 0; in < 8; in++){
      int col = nw + in * 8 + tig * 2;
      atomicAdd(&g_stats[layer][r][col][0], sum[in][0]);
      atomicAdd(&g_stats[layer][r][col][1], sq[in][0]);
      atomicAdd(&g_stats[layer][r][col + 1][0], sum[in][1]);
      atomicAdd(&g_stats[layer][r][col + 1][1], sq[in][1]);
    }
  }
}

// ---------------- GEMM layer 0 (gather, K = 3*128 + 16) ----------------
__global__ __launch_bounds__(256, 1)
void k_gemm0(const float* __restrict__ nf, const float* __restrict__ geo,
             const int* __restrict__ ei, const float* __restrict__ b0){
  extern __shared__ char bp[];
  __shared__ int sE[128], sN0[128], sN1[128], sN2[128];
  u32 sb = smem_u32(bp);

  int m0 = blockIdx.x << 7;
  if (m0 >= g_bnd[4]) return;
  int r = 0;
  #pragma unroll
  for (int q = 1; q < 4; q++) if (m0 >= g_bnd[q]) r = q;

  int tid = threadIdx.x, wid = tid >> 5, lane = tid & 31;
  int mw = (wid & 3) * 32, nw = (wid >> 2) * 64;

  if (tid < 128){
    int e = g_perm[m0 + tid];
    sE[tid] = e;
    int a = 0, b_ = 0, c = 0;
    if (e >= 0){ a = ei[e]; b_ = ei[E_ + e]; c = ei[2 * E_ + e]; }
    sN0[tid] = a; sN1[tid] = b_; sN2[tid] = c;
    ((float*)(bp + OFF_SSB))[tid] = b0[r * HID + tid];
  }
  __syncthreads();

  float acc[2][8][4];
  #pragma unroll
  for (int im = 0; im < 2; im++)
    #pragma unroll
    for (int in = 0; in < 8; in++)
      #pragma unroll
      for (int t = 0; t < 4; t++) acc[im][in][t] = 0.f;

  for (int ch = 0; ch < 4; ch++){
    if (ch){ __syncthreads(); }       // prior mma done before overwrite
    if (ch < 3){
      const int* nodes = (ch == 0) ? sN0 : ((ch == 1) ? sN1 : sN2);
      #pragma unroll
      for (int j = 0; j < 16; j++){
        int f = j * 256 + tid;
        int row = f >> 5, c4 = (f & 31) << 2;
        float4 v = make_float4(0.f, 0.f, 0.f, 0.f);
        if (sE[row] >= 0) v = *(const float4*)&nf[(size_t)nodes[row] * HID + c4];
        u32 o = (u32)(row * SA + c4) * 2;
        split_store4(bp, OFF_AHI + o, OFF_ALO + o, v);
      }
      const float4* sh = (const float4*)(g_W0h + (r * 3 + ch) * 16384);
      const float4* sl = (const float4*)(g_W0l + (r * 3 + ch) * 16384);
      for (int i = tid; i < 2048; i += 256){
        int row = i >> 4, seg = i & 15;
        u32 o = (u32)(row * SA + seg * 8) * 2;
        *(float4*)(bp + OFF_BHI + o) = sh[i];
        *(float4*)(bp + OFF_BLO + o) = sl[i];
      }
    } else {
      #pragma unroll
      for (int j = 0; j < 2; j++){
        int f = j * 256 + tid;
        int row = f >> 2, c4 = (f & 3) << 2;
        int e = sE[row];
        float4 v;
        #pragma unroll
        for (int t = 0; t < 4; t++){
          int col = c4 + t;
          (&v.x)[t] = (e >= 0 && col < GEO_) ? geo[(size_t)e * GEO_ + col] : 0.f;
        }
        u32 o = (u32)(row * SA + c4) * 2;
        split_store4(bp, OFF_AHI + o, OFF_ALO + o, v);
      }
      if (tid < 256){
        const float4* sh = (const float4*)(g_W0gh + r * 2048);
        const float4* sl = (const float4*)(g_W0gl + r * 2048);
        int row = tid >> 1, seg = tid & 1;
        u32 o = (u32)(row * SA + seg * 8) * 2;
        *(float4*)(bp + OFF_BHI + o) = sh[tid];
        *(float4*)(bp + OFF_BLO + o) = sl[tid];
      }
    }
    __syncthreads();
    mma_chunk(sb, mw, nw, lane, (ch < 3) ? 8 : 1, acc);
  }

  int nv = g_bnd[r] + g_cnt[r] - m0;
  nv = (nv < 0) ? 0 : ((nv > 128) ? 128 : nv);
  epilogue_mma(acc, bp, g_hA, m0, mw, nw, lane, r, 0, nv);
}

// ---------------- GEMM layers 1..3 ----------------
template<int LI>
__global__ __launch_bounds__(256, 1)
void k_gemml(const float* __restrict__ bArr){
  const float* hin  = (LI & 1) ? g_hA : g_hB;
  float*       hout = (LI & 1) ? g_hB : g_hA;
  extern __shared__ char bp[];
  u32 sb = smem_u32(bp);

  int m0 = blockIdx.x << 7;
  if (m0 >= g_bnd[4]) return;
  int r = 0;
  #pragma unroll
  for (int q = 1; q < 4; q++) if (m0 >= g_bnd[q]) r = q;

  int tid = threadIdx.x, wid = tid >> 5, lane = tid & 31;
  int mw = (wid & 3) * 32, nw = (wid >> 2) * 64;

  if (tid < 128){
    ((float*)(bp + OFF_SSC))[tid] = g_st[LI - 1][r][tid][0];
    ((float*)(bp + OFF_SSH))[tid] = g_st[LI - 1][r][tid][1];
    ((float*)(bp + OFF_SSB))[tid] = bArr[(r * 3 + (LI - 1)) * HID + tid];
  }
  __syncthreads();

  const float* ssc = (const float*)(bp + OFF_SSC);
  const float* ssh = (const float*)(bp + OFF_SSH);
  #pragma unroll
  for (int j = 0; j < 16; j++){
    int f = j * 256 + tid;
    int row = f >> 5, c4 = (f & 31) << 2;
    float4 h = *(const float4*)&hin[(size_t)(m0 + row) * HID + c4];
    float4 sc = *(const float4*)&ssc[c4];
    float4 sh = *(const float4*)&ssh[c4];
    float4 a;
    a.x = fmaxf(fmaf(h.x, sc.x, sh.x), 0.f);
    a.y = fmaxf(fmaf(h.y, sc.y, sh.y), 0.f);
    a.z = fmaxf(fmaf(h.z, sc.z, sh.z), 0.f);
    a.w = fmaxf(fmaf(h.w, sc.w, sh.w), 0.f);
    u32 o = (u32)(row * SA + c4) * 2;
    split_store4(bp, OFF_AHI + o, OFF_ALO + o, a);
  }
  {
    const float4* shp = (const float4*)(g_Wh + (r * 3 + (LI - 1)) * 16384);
    const float4* slp = (const float4*)(g_Wl + (r * 3 + (LI - 1)) * 16384);
    for (int i = tid; i < 2048; i += 256){
      int row = i >> 4, seg = i & 15;
      u32 o = (u32)(row * SA + seg * 8) * 2;
      *(float4*)(bp + OFF_BHI + o) = shp[i];
      *(float4*)(bp + OFF_BLO + o) = slp[i];
    }
  }
  __syncthreads();

  float acc[2][8][4];
  #pragma unroll
  for (int im = 0; im < 2; im++)
    #pragma unroll
    for (int in = 0; in < 8; in++)
      #pragma unroll
      for (int t = 0; t < 4; t++) acc[im][in][t] = 0.f;

  mma_chunk(sb, mw, nw, lane, 8, acc);

  int nv = g_bnd[r] + g_cnt[r] - m0;
  nv = (nv < 0) ? 0 : ((nv > 128) ? 128 : nv);
  epilogue_mma(acc, bp, hout, m0, mw, nw, lane, r, LI, nv);
}

// ---------------- BN finalize ----------------
__global__ void k_finalize(int layer, const float* __restrict__ gamma,
                           const float* __restrict__ beta){
  int t = threadIdx.x + blockIdx.x * blockDim.x;
  if (t >= 512) return;
  int r = t >> 7, c = t & 127;
  float cnt  = g_cntf[r];
  float mean = g_stats[layer][r][c][0] / cnt;
  float var  = fmaxf(g_stats[layer][r][c][1] / cnt - mean * mean, 0.f);
  float inv  = rsqrtf(var + 1e-5f);
  float s    = gamma[(r * 4 + layer) * HID + c] * inv;
  g_st[layer][r][c][0] = s;
  g_st[layer][r][c][1] = beta[(r * 4 + layer) * HID + c] - mean * s;
}

// ---------------- final scatter ----------------
__global__ void k_final(const int* __restrict__ ei, const float* __restrict__ att,
                        float* __restrict__ out){
  int t = blockIdx.x * 256 + threadIdx.x;
  int row = t >> 5;
  if (row >= g_bnd[4]) return;
  int e = g_perm[row];
  if (e < 0) return;
  int r = 0;
  #pragma unroll
  for (int q = 1; q < 4; q++) if (row >= g_bnd[q]) r = q;
  int c0 = (t & 31) << 2;
  float a = att[r];
  int i = ei[e];
  float4 h = *(const float4*)&g_hB[(size_t)row * HID + c0];
  float v0 = fmaxf(fmaf(h.x, g_st[3][r][c0 + 0][0], g_st[3][r][c0 + 0][1]), 0.f) * a;
  float v1 = fmaxf(fmaf(h.y, g_st[3][r][c0 + 1][0], g_st[3][r][c0 + 1][1]), 0.f) * a;
  float v2 = fmaxf(fmaf(h.z, g_st[3][r][c0 + 2][0], g_st[3][r][c0 + 2][1]), 0.f) * a;
  float v3 = fmaxf(fmaf(h.w, g_st[3][r][c0 + 3][0], g_st[3][r][c0 + 3][1]), 0.f) * a;
  atomicAdd(&out[(size_t)i * HID + c0 + 0], v0);
  atomicAdd(&out[(size_t)i * HID + c0 + 1], v1);
  atomicAdd(&out[(size_t)i * HID + c0 + 2], v2);
  atomicAdd(&out[(size_t)i * HID + c0 + 3], v3);
}

// ---------------- launch ----------------
extern "C" void kernel_launch(void* const* d_in, const int* in_sizes, int n_in,
                              void* d_out, int out_size){
  const float* nf    = (const float*)d_in[0];
  const float* geo   = (const float*)d_in[1];
  const int*   ei    = (const int*)d_in[2];
  const int*   eij   = (const int*)d_in[3];
  const int*   ejk   = (const int*)d_in[4];
  const int*   nei   = (const int*)d_in[5];
  const float* att   = (const float*)d_in[6];
  const float* W0    = (const float*)d_in[7];
  const float* b0    = (const float*)d_in[8];
  const float* W     = (const float*)d_in[9];
  const float* b     = (const float*)d_in[10];
  const float* gamma = (const float*)d_in[11];
  const float* beta  = (const float*)d_in[12];
  float* out = (float*)d_out;

  cudaFuncSetAttribute(k_gemm0,    cudaFuncAttributeMaxDynamicSharedMemorySize, SMEM_NEED);
  cudaFuncSetAttribute(k_gemml<1>, cudaFuncAttributeMaxDynamicSharedMemorySize, SMEM_NEED);
  cudaFuncSetAttribute(k_gemml<2>, cudaFuncAttributeMaxDynamicSharedMemorySize, SMEM_NEED);
  cudaFuncSetAttribute(k_gemml<3>, cudaFuncAttributeMaxDynamicSharedMemorySize, SMEM_NEED);

  k_init<<<(N_ * HID) / 256, 256>>>(out);
  k_prep<<<1600, 256>>>(W0, W);
  k_route<<<E_ / 256, 256>>>(eij, ejk, nei);
  k_offsets<<<1, 32>>>();
  k_perm<<<E_ / 256, 256>>>();

  k_gemm0<<<GRID_G, 256, SMEM_NEED>>>(nf, geo, ei, b0);
  k_finalize<<<1, 512>>>(0, gamma, beta);
  k_gemml<1><<<GRID_G, 256, SMEM_NEED>>>(b);
  k_finalize<<<1, 512>>>(1, gamma, beta);
  k_gemml<2><<<GRID_G, 256, SMEM_NEED>>>(b);
  k_finalize<<<1, 512>>>(2, gamma, beta);
  k_gemml<3><<<GRID_G, 256, SMEM_NEED>>>(b);
  k_finalize<<<1, 512>>>(3, gamma, beta);

  k_final<<<(ROWS_MAX * 32) / 256, 256>>>(ei, att, out);
}

// round 6
// speedup vs baseline: 1.1105x; 1.1105x over previous
#include <cuda_runtime.h>
#include <cuda_fp16.h>

#define HID 128
#define E_ 262144
#define N_ 32768
#define GEO_ 13
#define ROWS_MAX (E_ + 512)
#define GRID_G (ROWS_MAX / 128)

typedef unsigned long long u64;
typedef unsigned int u32;

// ---- dynamic smem layout ----
#define SA 136                     // padded row stride (elements); 272B rows, ldmatrix conflict-free
#define OFF_AHI 0                  // 128 x SA fp16 = 34816
#define OFF_ALO 34816
#define OFF_BHI 69632              // B_hi only: 128 x SA fp16
#define OFF_SSB 104448
#define OFF_SSC 104960
#define OFF_SSH 105472
#define SMEM_NEED 105984           // x2 CTAs = 212KB/SM -> occupancy 2

// ---------------- scratch (device globals; no allocation) ----------------
__device__ float g_hA[(size_t)ROWS_MAX * HID];
__device__ float g_hB[(size_t)ROWS_MAX * HID];
__device__ __half g_Wh[4 * 3 * 16384];    // layer weights fp16 [r*3+l][n][k]
__device__ __half g_W0h[4 * 3 * 16384];   // W0 k-chunks 0..2
__device__ __half g_W0gh[4 * 2048];       // W0 geo chunk [r][n][16]
__device__ int   g_perm[ROWS_MAX];
__device__ int   g_route[E_];
__device__ int   g_cnt[4];
__device__ int   g_cur[4];
__device__ int   g_bnd[5];
__device__ float g_cntf[4];
__device__ float g_stats[4][4][HID][2];
__device__ float g_st[4][4][HID][2];

// ---------------- helpers ----------------
__device__ __forceinline__ u32 smem_u32(const void* p){
  u32 a; asm("{ .reg .u64 t; cvta.to.shared.u64 t, %1; cvt.u32.u64 %0, t; }" : "=r"(a) : "l"(p));
  return a;
}
// split 4 floats into fp16 hi + fp16 residual, store packed
__device__ __forceinline__ void split_store4(char* bp, u32 offH, u32 offL, float4 v){
  __half2 h01 = __floats2half2_rn(v.x, v.y);
  __half2 h23 = __floats2half2_rn(v.z, v.w);
  float2 f01 = __half22float2(h01);
  float2 f23 = __half22float2(h23);
  __half2 l01 = __floats2half2_rn(v.x - f01.x, v.y - f01.y);
  __half2 l23 = __floats2half2_rn(v.z - f23.x, v.w - f23.y);
  *(uint2*)(bp + offH) = make_uint2(*(u32*)&h01, *(u32*)&h23);
  *(uint2*)(bp + offL) = make_uint2(*(u32*)&l01, *(u32*)&l23);
}
__device__ __forceinline__ void ldm4(u32& r0, u32& r1, u32& r2, u32& r3, u32 addr){
  asm volatile("ldmatrix.sync.aligned.m8n8.x4.shared.b16 {%0,%1,%2,%3}, [%4];"
               : "=r"(r0), "=r"(r1), "=r"(r2), "=r"(r3) : "r"(addr));
}
__device__ __forceinline__ void mma16816(float* d, const u32* a, u32 b0, u32 b1){
  asm volatile("mma.sync.aligned.m16n8k16.row.col.f32.f16.f16.f32 "
               "{%0,%1,%2,%3}, {%4,%5,%6,%7}, {%8,%9}, {%0,%1,%2,%3};"
               : "+f"(d[0]), "+f"(d[1]), "+f"(d[2]), "+f"(d[3])
               : "r"(a[0]), "r"(a[1]), "r"(a[2]), "r"(a[3]), "r"(b0), "r"(b1));
}

// ---------------- init ----------------
__global__ void k_init(float* __restrict__ out){
  int idx = blockIdx.x * 256 + threadIdx.x;
  if (idx < N_ * HID) out[idx] = 0.f;
  if (idx < ROWS_MAX) g_perm[idx] = -1;
  if (idx < 4 * 4 * HID * 2) ((float*)g_stats)[idx] = 0.f;
  if (idx < 4) { g_cnt[idx] = 0; g_cur[idx] = 0; }
}

// ---------------- weight preprocessing: fp16 hi images, plain [n][k] ----------------
__global__ void k_prep(const float* __restrict__ W0, const float* __restrict__ W){
  int idx = blockIdx.x * 256 + threadIdx.x;
  const int NL = 4 * 3 * 16384;
  if (idx < NL){
    int rl = idx / 16384, rem = idx & 16383;
    int n = rem >> 7, k = rem & 127;
    g_Wh[idx] = __float2half_rn(W[((size_t)(rl * 128 + n)) * 128 + k]);
  } else if (idx < 2 * NL){
    int t = idx - NL;
    int rc = t / 16384, rem = t & 16383;
    int r = rc / 3, c = rc % 3;
    int n = rem >> 7, k = rem & 127;
    g_W0h[t] = __float2half_rn(W0[((size_t)(r * 128 + n)) * 397 + c * 128 + k]);
  } else if (idx < 2 * NL + 4 * 2048){
    int t = idx - 2 * NL;
    int r = t / 2048, rem = t & 2047;
    int n = rem >> 4, k = rem & 15;
    int ko = 384 + k;
    float v = (ko < 397) ? W0[((size_t)(r * 128 + n)) * 397 + ko] : 0.f;
    g_W0gh[t] = __float2half_rn(v);
  }
}

// ---------------- routing / segmentation ----------------
__global__ void k_route(const int* __restrict__ eij, const int* __restrict__ ejk,
                        const int* __restrict__ nei_ptr){
  int e = blockIdx.x * 256 + threadIdx.x;
  if (e >= E_) return;
  int nei = nei_ptr[0];
  int r = ((eij[e] < nei) ? 0 : 2) | ((ejk[e] < nei) ? 0 : 1);
  g_route[e] = r;
  int lane = threadIdx.x & 31;
  #pragma unroll
  for (int rr = 0; rr < 4; rr++){
    unsigned m = __ballot_sync(0xFFFFFFFFu, r == rr);
    if (r == rr && lane == (__ffs(m) - 1)) atomicAdd(&g_cnt[rr], __popc(m));
  }
}
__global__ void k_offsets(){
  if (threadIdx.x == 0){
    int b = 0;
    #pragma unroll
    for (int r = 0; r < 4; r++){
      g_bnd[r] = b;
      int c = g_cnt[r];
      b += ((c + 127) / 128) * 128;
      g_cntf[r] = (c > 0) ? (float)c : 1.0f;
    }
    g_bnd[4] = b;
  }
}
__global__ void k_perm(){
  int e = blockIdx.x * 256 + threadIdx.x;
  if (e >= E_) return;
  int r = g_route[e];
  int lane = threadIdx.x & 31;
  #pragma unroll
  for (int rr = 0; rr < 4; rr++){
    unsigned m = __ballot_sync(0xFFFFFFFFu, r == rr);
    if (r == rr){
      int leader = __ffs(m) - 1;
      int base = 0;
      if (lane == leader) base = atomicAdd(&g_cur[rr], __popc(m));
      base = __shfl_sync(m, base, leader);
      unsigned lt = (lane == 0) ? 0u : (0xFFFFFFFFu >> (32 - lane));
      g_perm[g_bnd[rr] + base + __popc(m & lt)] = e;
    }
  }
}

// ---------------- HMMA mainloop: 2 products (A_hi + A_lo) x B_hi ----------------
__device__ __forceinline__ void mma_chunk(u32 sb, int mw, int nw, int lane, int nk,
                                          float acc[2][8][4]){
  for (int ks = 0; ks < nk; ks++){
    int k0 = ks * 16;
    u32 ah[2][4], al[2][4];
    #pragma unroll
    for (int im = 0; im < 2; im++){
      int row = mw + im * 16 + (lane & 15);
      int col = k0 + ((lane >> 4) << 3);
      u32 off = (u32)(row * SA + col) * 2;
      ldm4(ah[im][0], ah[im][1], ah[im][2], ah[im][3], sb + OFF_AHI + off);
      ldm4(al[im][0], al[im][1], al[im][2], al[im][3], sb + OFF_ALO + off);
    }
    u32 b[8][2];
    int brow = nw + ((lane >> 4) << 3) + (lane & 7);
    int bcol = k0 + (((lane >> 3) & 1) << 3);
    #pragma unroll
    for (int g = 0; g < 4; g++){
      u32 off = (u32)((brow + g * 16) * SA + bcol) * 2;
      ldm4(b[2*g][0], b[2*g][1], b[2*g+1][0], b[2*g+1][1], sb + OFF_BHI + off);
    }
    #pragma unroll
    for (int im = 0; im < 2; im++)
      #pragma unroll
      for (int in = 0; in < 8; in++){
        mma16816(acc[im][in], ah[im], b[in][0], b[in][1]);
        mma16816(acc[im][in], al[im], b[in][0], b[in][1]);
      }
  }
}

// ---------------- epilogue: bias + store + fused BN stats ----------------
__device__ __forceinline__ void epilogue_mma(float acc[2][8][4], char* bp,
                                             float* __restrict__ hout,
                                             int m0, int mw, int nw, int lane,
                                             int r, int layer, int nval){
  int gid = lane >> 2, tig = lane & 3;
  const float* ssb = (const float*)(bp + OFF_SSB);
  float sum[8][2], sq[8][2];
  #pragma unroll
  for (int in = 0; in < 8; in++){ sum[in][0] = sum[in][1] = sq[in][0] = sq[in][1] = 0.f; }
  #pragma unroll
  for (int im = 0; im < 2; im++){
    int lr0 = mw + im * 16 + gid;
    bool v0 = lr0 < nval, v1 = (lr0 + 8) < nval;
    #pragma unroll
    for (int in = 0; in < 8; in++){
      float* d = acc[im][in];
      int col = nw + in * 8 + tig * 2;
      float b0 = ssb[col], b1 = ssb[col + 1];
      float e0 = d[0] + b0, e1 = d[1] + b1, e2 = d[2] + b0, e3 = d[3] + b1;
      *(float2*)&hout[(size_t)(m0 + lr0) * HID + col]     = make_float2(e0, e1);
      *(float2*)&hout[(size_t)(m0 + lr0 + 8) * HID + col] = make_float2(e2, e3);
      float m0v = v0 ? e0 : 0.f, m1v = v0 ? e1 : 0.f;
      float m2v = v1 ? e2 : 0.f, m3v = v1 ? e3 : 0.f;
      sum[in][0] += m0v + m2v; sum[in][1] += m1v + m3v;
      sq[in][0]  += m0v * m0v + m2v * m2v;
      sq[in][1]  += m1v * m1v + m3v * m3v;
    }
  }
  #pragma unroll
  for (int off = 4; off <= 16; off <<= 1){
    #pragma unroll
    for (int in = 0; in < 8; in++){
      sum[in][0] += __shfl_xor_sync(0xFFFFFFFFu, sum[in][0], off);
      sum[in][1] += __shfl_xor_sync(0xFFFFFFFFu, sum[in][1], off);
      sq[in][0]  += __shfl_xor_sync(0xFFFFFFFFu, sq[in][0], off);
      sq[in][1]  += __shfl_xor_sync(0xFFFFFFFFu, sq[in][1], off);
    }
  }
  if (gid == 0){
    #pragma unroll
    for (int in = 0; in < 8; in++){
      int col = nw + in * 8 + tig * 2;
      atomicAdd(&g_stats[layer][r][col][0], sum[in][0]);
      atomicAdd(&g_stats[layer][r][col][1], sq[in][0]);
      atomicAdd(&g_stats[layer][r][col + 1][0], sum[in][1]);
      atomicAdd(&g_stats[layer][r][col + 1][1], sq[in][1]);
    }
  }
}

// ---------------- GEMM layer 0 (gather, K = 3*128 + 16) ----------------
__global__ __launch_bounds__(256, 2)
void k_gemm0(const float* __restrict__ nf, const float* __restrict__ geo,
             const int* __restrict__ ei, const float* __restrict__ b0){
  extern __shared__ char bp[];
  __shared__ int sE[128], sN0[128], sN1[128], sN2[128];
  u32 sb = smem_u32(bp);

  int m0 = blockIdx.x << 7;
  if (m0 >= g_bnd[4]) return;
  int r = 0;
  #pragma unroll
  for (int q = 1; q < 4; q++) if (m0 >= g_bnd[q]) r = q;

  int tid = threadIdx.x, wid = tid >> 5, lane = tid & 31;
  int mw = (wid & 3) * 32, nw = (wid >> 2) * 64;

  if (tid < 128){
    int e = g_perm[m0 + tid];
    sE[tid] = e;
    int a = 0, b_ = 0, c = 0;
    if (e >= 0){ a = ei[e]; b_ = ei[E_ + e]; c = ei[2 * E_ + e]; }
    sN0[tid] = a; sN1[tid] = b_; sN2[tid] = c;
    ((float*)(bp + OFF_SSB))[tid] = b0[r * HID + tid];
  }
  __syncthreads();

  float acc[2][8][4];
  #pragma unroll
  for (int im = 0; im < 2; im++)
    #pragma unroll
    for (int in = 0; in < 8; in++)
      #pragma unroll
      for (int t = 0; t < 4; t++) acc[im][in][t] = 0.f;

  for (int ch = 0; ch < 4; ch++){
    if (ch){ __syncthreads(); }       // prior mma reads done before overwrite
    if (ch < 3){
      const int* nodes = (ch == 0) ? sN0 : ((ch == 1) ? sN1 : sN2);
      #pragma unroll
      for (int j = 0; j < 16; j++){
        int f = j * 256 + tid;
        int row = f >> 5, c4 = (f & 31) << 2;
        float4 v = make_float4(0.f, 0.f, 0.f, 0.f);
        if (sE[row] >= 0) v = *(const float4*)&nf[(size_t)nodes[row] * HID + c4];
        u32 o = (u32)(row * SA + c4) * 2;
        split_store4(bp, OFF_AHI + o, OFF_ALO + o, v);
      }
      const float4* sh = (const float4*)(g_W0h + (r * 3 + ch) * 16384);
      for (int i = tid; i < 2048; i += 256){
        int row = i >> 4, seg = i & 15;
        *(float4*)(bp + OFF_BHI + (u32)(row * SA + seg * 8) * 2) = sh[i];
      }
    } else {
      #pragma unroll
      for (int j = 0; j < 2; j++){
        int f = j * 256 + tid;
        int row = f >> 2, c4 = (f & 3) << 2;
        int e = sE[row];
        float4 v;
        #pragma unroll
        for (int t = 0; t < 4; t++){
          int col = c4 + t;
          (&v.x)[t] = (e >= 0 && col < GEO_) ? geo[(size_t)e * GEO_ + col] : 0.f;
        }
        u32 o = (u32)(row * SA + c4) * 2;
        split_store4(bp, OFF_AHI + o, OFF_ALO + o, v);
      }
      {
        const float4* sh = (const float4*)(g_W0gh + r * 2048);
        int row = tid >> 1, seg = tid & 1;
        *(float4*)(bp + OFF_BHI + (u32)(row * SA + seg * 8) * 2) = sh[tid];
      }
    }
    __syncthreads();
    mma_chunk(sb, mw, nw, lane, (ch < 3) ? 8 : 1, acc);
  }

  int nv = g_bnd[r] + g_cnt[r] - m0;
  nv = (nv < 0) ? 0 : ((nv > 128) ? 128 : nv);
  epilogue_mma(acc, bp, g_hA, m0, mw, nw, lane, r, 0, nv);
}

// ---------------- GEMM layers 1..3 ----------------
template<int LI>
__global__ __launch_bounds__(256, 2)
void k_gemml(const float* __restrict__ bArr){
  const float* hin  = (LI & 1) ? g_hA : g_hB;
  float*       hout = (LI & 1) ? g_hB : g_hA;
  extern __shared__ char bp[];
  u32 sb = smem_u32(bp);

  int m0 = blockIdx.x << 7;
  if (m0 >= g_bnd[4]) return;
  int r = 0;
  #pragma unroll
  for (int q = 1; q < 4; q++) if (m0 >= g_bnd[q]) r = q;

  int tid = threadIdx.x, wid = tid >> 5, lane = tid & 31;
  int mw = (wid & 3) * 32, nw = (wid >> 2) * 64;

  if (tid < 128){
    ((float*)(bp + OFF_SSC))[tid] = g_st[LI - 1][r][tid][0];
    ((float*)(bp + OFF_SSH))[tid] = g_st[LI - 1][r][tid][1];
    ((float*)(bp + OFF_SSB))[tid] = bArr[(r * 3 + (LI - 1)) * HID + tid];
  }
  __syncthreads();

  const float* ssc = (const float*)(bp + OFF_SSC);
  const float* ssh = (const float*)(bp + OFF_SSH);
  #pragma unroll
  for (int j = 0; j < 16; j++){
    int f = j * 256 + tid;
    int row = f >> 5, c4 = (f & 31) << 2;
    float4 h = *(const float4*)&hin[(size_t)(m0 + row) * HID + c4];
    float4 sc = *(const float4*)&ssc[c4];
    float4 sh = *(const float4*)&ssh[c4];
    float4 a;
    a.x = fmaxf(fmaf(h.x, sc.x, sh.x), 0.f);
    a.y = fmaxf(fmaf(h.y, sc.y, sh.y), 0.f);
    a.z = fmaxf(fmaf(h.z, sc.z, sh.z), 0.f);
    a.w = fmaxf(fmaf(h.w, sc.w, sh.w), 0.f);
    u32 o = (u32)(row * SA + c4) * 2;
    split_store4(bp, OFF_AHI + o, OFF_ALO + o, a);
  }
  {
    const float4* shp = (const float4*)(g_Wh + (r * 3 + (LI - 1)) * 16384);
    for (int i = tid; i < 2048; i += 256){
      int row = i >> 4, seg = i & 15;
      *(float4*)(bp + OFF_BHI + (u32)(row * SA + seg * 8) * 2) = shp[i];
    }
  }
  __syncthreads();

  float acc[2][8][4];
  #pragma unroll
  for (int im = 0; im < 2; im++)
    #pragma unroll
    for (int in = 0; in < 8; in++)
      #pragma unroll
      for (int t = 0; t < 4; t++) acc[im][in][t] = 0.f;

  mma_chunk(sb, mw, nw, lane, 8, acc);

  int nv = g_bnd[r] + g_cnt[r] - m0;
  nv = (nv < 0) ? 0 : ((nv > 128) ? 128 : nv);
  epilogue_mma(acc, bp, hout, m0, mw, nw, lane, r, LI, nv);
}

// ---------------- BN finalize ----------------
__global__ void k_finalize(int layer, const float* __restrict__ gamma,
                           const float* __restrict__ beta){
  int t = threadIdx.x + blockIdx.x * blockDim.x;
  if (t >= 512) return;
  int r = t >> 7, c = t & 127;
  float cnt  = g_cntf[r];
  float mean = g_stats[layer][r][c][0] / cnt;
  float var  = fmaxf(g_stats[layer][r][c][1] / cnt - mean * mean, 0.f);
  float inv  = rsqrtf(var + 1e-5f);
  float s    = gamma[(r * 4 + layer) * HID + c] * inv;
  g_st[layer][r][c][0] = s;
  g_st[layer][r][c][1] = beta[(r * 4 + layer) * HID + c] - mean * s;
}

// ---------------- final scatter ----------------
__global__ void k_final(const int* __restrict__ ei, const float* __restrict__ att,
                        float* __restrict__ out){
  int t = blockIdx.x * 256 + threadIdx.x;
  int row = t >> 5;
  if (row >= g_bnd[4]) return;
  int e = g_perm[row];
  if (e < 0) return;
  int r = 0;
  #pragma unroll
  for (int q = 1; q < 4; q++) if (row >= g_bnd[q]) r = q;
  int c0 = (t & 31) << 2;
  float a = att[r];
  int i = ei[e];
  float4 h = *(const float4*)&g_hB[(size_t)row * HID + c0];
  float v0 = fmaxf(fmaf(h.x, g_st[3][r][c0 + 0][0], g_st[3][r][c0 + 0][1]), 0.f) * a;
  float v1 = fmaxf(fmaf(h.y, g_st[3][r][c0 + 1][0], g_st[3][r][c0 + 1][1]), 0.f) * a;
  float v2 = fmaxf(fmaf(h.z, g_st[3][r][c0 + 2][0], g_st[3][r][c0 + 2][1]), 0.f) * a;
  float v3 = fmaxf(fmaf(h.w, g_st[3][r][c0 + 3][0], g_st[3][r][c0 + 3][1]), 0.f) * a;
  atomicAdd(&out[(size_t)i * HID + c0 + 0], v0);
  atomicAdd(&out[(size_t)i * HID + c0 + 1], v1);
  atomicAdd(&out[(size_t)i * HID + c0 + 2], v2);
  atomicAdd(&out[(size_t)i * HID + c0 + 3], v3);
}

// ---------------- launch ----------------
extern "C" void kernel_launch(void* const* d_in, const int* in_sizes, int n_in,
                              void* d_out, int out_size){
  const float* nf    = (const float*)d_in[0];
  const float* geo   = (const float*)d_in[1];
  const int*   ei    = (const int*)d_in[2];
  const int*   eij   = (const int*)d_in[3];
  const int*   ejk   = (const int*)d_in[4];
  const int*   nei   = (const int*)d_in[5];
  const float* att   = (const float*)d_in[6];
  const float* W0    = (const float*)d_in[7];
  const float* b0    = (const float*)d_in[8];
  const float* W     = (const float*)d_in[9];
  const float* b     = (const float*)d_in[10];
  const float* gamma = (const float*)d_in[11];
  const float* beta  = (const float*)d_in[12];
  float* out = (float*)d_out;

  cudaFuncSetAttribute(k_gemm0,    cudaFuncAttributeMaxDynamicSharedMemorySize, SMEM_NEED);
  cudaFuncSetAttribute(k_gemml<1>, cudaFuncAttributeMaxDynamicSharedMemorySize, SMEM_NEED);
  cudaFuncSetAttribute(k_gemml<2>, cudaFuncAttributeMaxDynamicSharedMemorySize, SMEM_NEED);
  cudaFuncSetAttribute(k_gemml<3>, cudaFuncAttributeMaxDynamicSharedMemorySize, SMEM_NEED);

  k_init<<<(N_ * HID) / 256, 256>>>(out);
  k_prep<<<1568, 256>>>(W0, W);
  k_route<<<E_ / 256, 256>>>(eij, ejk, nei);
  k_offsets<<<1, 32>>>();
  k_perm<<<E_ / 256, 256>>>();

  k_gemm0<<<GRID_G, 256, SMEM_NEED>>>(nf, geo, ei, b0);
  k_finalize<<<1, 512>>>(0, gamma, beta);
  k_gemml<1><<<GRID_G, 256, SMEM_NEED>>>(b);
  k_finalize<<<1, 512>>>(1, gamma, beta);
  k_gemml<2><<<GRID_G, 256, SMEM_NEED>>>(b);
  k_finalize<<<1, 512>>>(2, gamma, beta);
  k_gemml<3><<<GRID_G, 256, SMEM_NEED>>>(b);
  k_finalize<<<1, 512>>>(3, gamma, beta);

  k_final<<<(ROWS_MAX * 32) / 256, 256>>>(ei, att, out);
}